// round 16
// baseline (speedup 1.0000x reference)
#include <cuda_runtime.h>
#include <cuda_bf16.h>
#include <cstdint>

// ---------------------------------------------------------------------------
// GCN 3-layer forward on GB300.
// R16: drop the g_sd intermediate — place re-decodes edge_index (L2-resident)
// directly, deleting ~25.6MB of write+read traffic from prep.
// GEMMs: cp.async double-buffered k-chunk pipeline (R15 champion form).
// Relu folded into aggregate64 epilogue.
// ---------------------------------------------------------------------------

#define N_NODES 100000
#define N_EDGES 1600000
#define SCAN_BS 1024
#define SCAN_NB ((N_NODES + SCAN_BS - 1) / SCAN_BS)

__device__ __align__(16) float  g_h[N_NODES * 64];
__device__ __align__(16) float  g_aggA[N_NODES * 64];
__device__ __align__(16) float  g_aggB[N_NODES * 64];
__device__ float  g_dinv[N_NODES];
__device__ int    g_cnt[N_NODES];
__device__ int    g_rowptr[N_NODES + 1];
__device__ int    g_cursor[N_NODES];
__device__ int    g_bsum[SCAN_NB];
__device__ __align__(8) float2 g_epack[N_EDGES];  // CSR: {src bits, coef}
__device__ int    g_is64;

#define FMA2(d, a, b) \
    asm("fma.rn.f32x2 %0, %1, %2, %0;" : "+l"(d) : "l"(a), "l"(b))
#define PACKXX(d, x) \
    asm("mov.b64 %0, {%1, %1};" : "=l"(d) : "f"(x))
#define CP_ASYNC16(dst, src) \
    asm volatile("cp.async.ca.shared.global [%0], [%1], 16;" \
                 :: "r"(dst), "l"(src) : "memory")
#define CP_COMMIT() asm volatile("cp.async.commit_group;" ::: "memory")
#define CP_WAIT(nn) asm volatile("cp.async.wait_group %0;" :: "n"(nn) : "memory")

// ---------------------------------------------------------------------------
// Prep
// ---------------------------------------------------------------------------
__global__ void detect_zero_kernel(const int* __restrict__ w, int n) {
    int i = blockIdx.x * blockDim.x + threadIdx.x;
    if (i < n) g_cnt[i] = 0;
    if (blockIdx.x == 0) {
        __shared__ int nonzero;
        if (threadIdx.x == 0) nonzero = 0;
        __syncthreads();
        if (w[2 * threadIdx.x + 1] != 0) atomicOr(&nonzero, 1);
        __syncthreads();
        if (threadIdx.x == 0) g_is64 = (nonzero == 0) ? 1 : 0;
    }
}

// Pure read + histogram (no intermediate store).
__global__ void hist_kernel(const void* __restrict__ ei, int ne) {
    int e = blockIdx.x * blockDim.x + threadIdx.x;
    if (e >= ne) return;
    int d;
    if (g_is64) {
        d = (int)((const long long*)ei)[ne + e];
    } else {
        d = ((const int*)ei)[ne + e];
    }
    atomicAdd(&g_cnt[d], 1);
}

__global__ void scan1_kernel(int n) {
    __shared__ int sm[SCAN_BS];
    int t = threadIdx.x;
    int i = blockIdx.x * SCAN_BS + t;
    int v = (i < n) ? g_cnt[i] : 0;
    sm[t] = v;
    __syncthreads();
    for (int off = 1; off < SCAN_BS; off <<= 1) {
        int u = (t >= off) ? sm[t - off] : 0;
        __syncthreads();
        sm[t] += u;
        __syncthreads();
    }
    if (i < n) {
        g_rowptr[i] = sm[t] - v;
        g_dinv[i]   = rsqrtf((float)v + 1.0f);
    }
    if (t == SCAN_BS - 1) g_bsum[blockIdx.x] = sm[t];
}

__global__ void scan3_kernel(int n, int ne) {
    __shared__ int s_pref;
    const int t = threadIdx.x;
    const int b = (blockIdx.x * 256) / SCAN_BS;
    if (t < 32) {
        int v = 0;
        for (int j = t; j < b; j += 32) v += g_bsum[j];
#pragma unroll
        for (int o = 16; o; o >>= 1) v += __shfl_down_sync(0xffffffffu, v, o);
        if (t == 0) s_pref = v;
    }
    __syncthreads();
    int i = blockIdx.x * 256 + t;
    if (i < n) {
        int r = g_rowptr[i] + s_pref;
        g_rowptr[i] = r;
        g_cursor[i] = r;
    }
    if (i == 0) g_rowptr[n] = ne;
}

// Re-decodes edge_index directly (L2-resident after hist).
__global__ void place_kernel(const void* __restrict__ ei, int ne) {
    int e = blockIdx.x * blockDim.x + threadIdx.x;
    if (e >= ne) return;
    int s, d;
    if (g_is64) {
        const long long* p = (const long long*)ei;
        s = (int)p[e];
        d = (int)p[ne + e];
    } else {
        const int* p = (const int*)ei;
        s = p[e];
        d = p[ne + e];
    }
    int pos = atomicAdd(&g_cursor[d], 1);
    g_epack[pos] = make_float2(__int_as_float(s), g_dinv[s] * g_dinv[d]);
}

// ---------------------------------------------------------------------------
// Pipelined register-blocked GEMM, DOUT=64, 128 threads (R15 champion form).
// ---------------------------------------------------------------------------
template <int DIN>
__global__ void __launch_bounds__(128) gemm64p_kernel(const float* __restrict__ in,
                                                      const float* __restrict__ W,
                                                      float* __restrict__ h_out,
                                                      int n)
{
    constexpr int DOUT = 64;
    constexpr int TILE_R = 128;
    constexpr int KC = 32;
    constexpr int XS = KC + 4;
    constexpr int NCH = DIN / KC;
    constexpr int CHUNK_V4 = TILE_R * KC / 4;

    extern __shared__ float sm[];
    float* sW = sm;
    float* sX = sm + DIN * DOUT;

    const int tid  = threadIdx.x;
    const int row0 = blockIdx.x * TILE_R;
    const unsigned int sx_base = (unsigned int)__cvta_generic_to_shared(sX);

    const float4* Wv  = (const float4*)W;
    float4*       sWv = (float4*)sW;
    for (int i = tid; i < DIN * DOUT / 4; i += 128) sWv[i] = Wv[i];

    auto stage = [&](int ck, int buf) {
#pragma unroll
        for (int i = tid; i < CHUNK_V4; i += 128) {
            int r = i >> 3;
            int q = i & 7;
            int gr = row0 + r;
            if (gr < n) {
                unsigned int dst = sx_base +
                    (unsigned int)((buf * TILE_R * XS + r * XS + q * 4) * 4);
                const float* src = &in[gr * DIN + ck * KC + q * 4];
                CP_ASYNC16(dst, src);
            }
        }
        CP_COMMIT();
    };

    stage(0, 0);

    const int cg = tid & 7;
    const int tr = tid >> 3;

    unsigned long long acc[8][4];
#pragma unroll
    for (int j = 0; j < 8; j++)
#pragma unroll
        for (int p = 0; p < 4; p++) acc[j][p] = 0ULL;

    const ulonglong2* wv = (const ulonglong2*)sW;

    for (int ck = 0; ck < NCH; ck++) {
        if (ck + 1 < NCH) {
            stage(ck + 1, (ck + 1) & 1);
            CP_WAIT(1);
        } else {
            CP_WAIT(0);
        }
        __syncthreads();

        const float* xbase = sX + (ck & 1) * TILE_R * XS + tr * XS;
#pragma unroll
        for (int k = 0; k < KC; k++) {
            ulonglong2 wA = wv[(ck * KC + k) * (DOUT / 4) + cg];
            ulonglong2 wB = wv[(ck * KC + k) * (DOUT / 4) + 8 + cg];
#pragma unroll
            for (int j = 0; j < 8; j++) {
                float xv = xbase[j * 16 * XS + k];
                unsigned long long xx;
                PACKXX(xx, xv);
                FMA2(acc[j][0], xx, wA.x);
                FMA2(acc[j][1], xx, wA.y);
                FMA2(acc[j][2], xx, wB.x);
                FMA2(acc[j][3], xx, wB.y);
            }
        }
        __syncthreads();
    }

#pragma unroll
    for (int j = 0; j < 8; j++) {
        int r = row0 + tr + 16 * j;
        if (r < n) {
            ulonglong2* o = (ulonglong2*)&h_out[r * DOUT + cg * 4];
            o[0] = make_ulonglong2(acc[j][0], acc[j][1]);
            o[8] = make_ulonglong2(acc[j][2], acc[j][3]);
        }
    }
}

// ---------------------------------------------------------------------------
// GEMM for DOUT=40 (layer 3) — smem-walk version. Input already relu'd.
// ---------------------------------------------------------------------------
template <int DIN, int DOUT, int CGROUPS, int TILE_R>
__global__ void gemm_kernel(const float* __restrict__ in,
                            const float* __restrict__ W,
                            float* __restrict__ h_out,
                            int n)
{
    constexpr int CP = DOUT / CGROUPS;
    constexpr int XS = DIN + 1;
    extern __shared__ float sm[];
    float* sW = sm;
    float* sX = sm + DIN * DOUT;

    const int tid  = threadIdx.x;
    const int nthr = blockDim.x;
    const int row0 = blockIdx.x * TILE_R;

    for (int i = tid; i < DIN * DOUT; i += nthr) sW[i] = W[i];
    for (int i = tid; i < TILE_R * DIN; i += nthr) {
        int r = i / DIN;
        int k = i - r * DIN;
        int gr = row0 + r;
        float v = 0.0f;
        if (gr < n) v = in[gr * DIN + k];
        sX[r * XS + k] = v;
    }
    __syncthreads();

    const int rl = tid / CGROUPS;
    const int cg = tid - rl * CGROUPS;
    const int c0 = cg * CP;

    float acc[CP];
#pragma unroll
    for (int j = 0; j < CP; j++) acc[j] = 0.0f;

    const float* xrow = &sX[rl * XS];
#pragma unroll 4
    for (int k = 0; k < DIN; k++) {
        float xv = xrow[k];
        const float4* wrow = reinterpret_cast<const float4*>(&sW[k * DOUT + c0]);
#pragma unroll
        for (int j4 = 0; j4 < CP / 4; j4++) {
            float4 w = wrow[j4];
            acc[j4 * 4 + 0] = fmaf(xv, w.x, acc[j4 * 4 + 0]);
            acc[j4 * 4 + 1] = fmaf(xv, w.y, acc[j4 * 4 + 1]);
            acc[j4 * 4 + 2] = fmaf(xv, w.z, acc[j4 * 4 + 2]);
            acc[j4 * 4 + 3] = fmaf(xv, w.w, acc[j4 * 4 + 3]);
        }
    }

    const int r = row0 + rl;
    if (r < n) {
#pragma unroll
        for (int j4 = 0; j4 < CP / 4; j4++) {
            float4 hv = make_float4(acc[j4 * 4 + 0], acc[j4 * 4 + 1],
                                    acc[j4 * 4 + 2], acc[j4 * 4 + 3]);
            *reinterpret_cast<float4*>(&h_out[r * DOUT + c0 + j4 * 4]) = hv;
        }
    }
}

// ---------------------------------------------------------------------------
// Aggregation DOUT=64 (+relu in epilogue).
// ---------------------------------------------------------------------------
__global__ void aggregate64_kernel(const float* __restrict__ h,
                                   const float* __restrict__ bias,
                                   float* __restrict__ out,
                                   int n)
{
    int w = (blockIdx.x * blockDim.x + threadIdx.x) >> 5;
    if (w >= n) return;
    int lane = threadIdx.x & 31;
    int half = lane >> 4;
    int sub  = lane & 15;

    int c0 = g_rowptr[w];
    int c1 = g_rowptr[w + 1];

    const float4* hp4 = (const float4*)h;
    float4 acc = make_float4(0.f, 0.f, 0.f, 0.f);

#pragma unroll 2
    for (int i = c0; i < c1; i += 2) {
        int e = i + half;
        if (e < c1) {
            float2 pk = g_epack[e];
            int   s = __float_as_int(pk.x);
            float c = pk.y;
            float4 v = hp4[s * 16 + sub];
            acc.x = fmaf(v.x, c, acc.x);
            acc.y = fmaf(v.y, c, acc.y);
            acc.z = fmaf(v.z, c, acc.z);
            acc.w = fmaf(v.w, c, acc.w);
        }
    }
    acc.x += __shfl_xor_sync(0xffffffffu, acc.x, 16);
    acc.y += __shfl_xor_sync(0xffffffffu, acc.y, 16);
    acc.z += __shfl_xor_sync(0xffffffffu, acc.z, 16);
    acc.w += __shfl_xor_sync(0xffffffffu, acc.w, 16);

    float di  = g_dinv[w];
    float di2 = di * di;
    float4 hs = hp4[w * 16 + sub];
    float4 bv = ((const float4*)bias)[sub];
    float4 r;
    r.x = fmaxf(fmaf(hs.x, di2, acc.x) + bv.x, 0.f);
    r.y = fmaxf(fmaf(hs.y, di2, acc.y) + bv.y, 0.f);
    r.z = fmaxf(fmaf(hs.z, di2, acc.z) + bv.z, 0.f);
    r.w = fmaxf(fmaf(hs.w, di2, acc.w) + bv.w, 0.f);
    if (half == 0) ((float4*)out)[w * 16 + sub] = r;
}

// ---------------------------------------------------------------------------
// Aggregation DOUT=40 (final output — NO relu).
// ---------------------------------------------------------------------------
__global__ void aggregate40_kernel(const float* __restrict__ h,
                                   const float* __restrict__ bias,
                                   float* __restrict__ out,
                                   int n)
{
    int w = (blockIdx.x * blockDim.x + threadIdx.x) >> 5;
    if (w >= n) return;
    int lane = threadIdx.x & 31;

    int c0 = g_rowptr[w];
    int c1 = g_rowptr[w + 1];
    bool hi = (lane < 8);

    float a0 = 0.0f, a1 = 0.0f;
    for (int i = c0; i < c1; i++) {
        float2 pk = g_epack[i];
        int   s = __float_as_int(pk.x);
        float c = pk.y;
        const float* hr = &h[s * 40];
        a0 = fmaf(hr[lane], c, a0);
        if (hi) a1 = fmaf(hr[32 + lane], c, a1);
    }

    float di  = g_dinv[w];
    float di2 = di * di;
    const float* hs = &h[w * 40];
    out[w * 40 + lane] = fmaf(hs[lane], di2, a0) + bias[lane];
    if (hi)
        out[w * 40 + 32 + lane] = fmaf(hs[32 + lane], di2, a1) + bias[32 + lane];
}

// ---------------------------------------------------------------------------
// Launch (single stream; gemm1 at launch slot 4 for ncu visibility)
// ---------------------------------------------------------------------------
extern "C" void kernel_launch(void* const* d_in, const int* in_sizes, int n_in,
                              void* d_out, int out_size)
{
    const float* x  = (const float*)d_in[0];
    const void*  ei = d_in[1];
    const float* W1 = (const float*)d_in[2];
    const float* b1 = (const float*)d_in[3];
    const float* W2 = (const float*)d_in[4];
    const float* b2 = (const float*)d_in[5];
    const float* W3 = (const float*)d_in[6];
    const float* b3 = (const float*)d_in[7];
    float* out = (float*)d_out;

    const int N = in_sizes[0] / 128;   // 100000
    const int E = in_sizes[1] / 2;     // 1600000

    float *h, *aggA, *aggB;
    cudaGetSymbolAddress((void**)&h,    g_h);
    cudaGetSymbolAddress((void**)&aggA, g_aggA);
    cudaGetSymbolAddress((void**)&aggB, g_aggB);

    constexpr int TRB = 128;
    const int g2_grid  = (N + TRB - 1) / TRB;
    const int agg_grid = (N * 32 + 255) / 256;
    const int smem1 = (128 * 64 + 2 * TRB * 36) * (int)sizeof(float);  // 68KB
    const int smem2 = (64 * 64 + 2 * TRB * 36) * (int)sizeof(float);   // 52KB
    cudaFuncSetAttribute(gemm64p_kernel<128>,
                         cudaFuncAttributeMaxDynamicSharedMemorySize, smem1);
    cudaFuncSetAttribute(gemm64p_kernel<64>,
                         cudaFuncAttributeMaxDynamicSharedMemorySize, smem2);

    // --- prep (launches 1-3) ---
    detect_zero_kernel<<<(N + 255) / 256, 256>>>((const int*)ei, N);
    hist_kernel<<<(E + 255) / 256, 256>>>(ei, E);
    const int nb = (N + SCAN_BS - 1) / SCAN_BS;
    scan1_kernel<<<nb, SCAN_BS>>>(N);

    // --- launch 4: GEMM1 (independent of CSR prep; ncu captures slot 4) ---
    gemm64p_kernel<128><<<g2_grid, 128, smem1>>>(x, W1, h, N);

    // --- prep tail (launches 5-6) ---
    scan3_kernel<<<(N + 255) / 256, 256>>>(N, E);
    place_kernel<<<(E + 255) / 256, 256>>>(ei, E);

    // --- layer 1 aggregation (writes relu'd aggA) ---
    aggregate64_kernel<<<agg_grid, 256>>>(h, b1, aggA, N);

    // --- layer 2: 64 -> 64 ---
    gemm64p_kernel<64><<<g2_grid, 128, smem2>>>(aggA, W2, h, N);
    aggregate64_kernel<<<agg_grid, 256>>>(h, b2, aggB, N);

    // --- layer 3: 64 -> 40 (aggB already relu'd) ---
    constexpr int TR3 = 64;
    const int g3_grid = (N + TR3 - 1) / TR3;
    const int smem3 = (64 * 40 + TR3 * (64 + 1)) * (int)sizeof(float);
    gemm_kernel<64, 40, 5, TR3><<<g3_grid, TR3 * 5, smem3>>>(aggB, W3, h, N);
    aggregate40_kernel<<<agg_grid, 256>>>(h, b3, out, N);
}

// round 17
// speedup vs baseline: 1.0376x; 1.0376x over previous
#include <cuda_runtime.h>
#include <cuda_bf16.h>
#include <cuda_fp16.h>
#include <cstdint>

// ---------------------------------------------------------------------------
// GCN 3-layer forward on GB300.
// R17: message matrix h stored in FP16 (consumed only by the gather/self-loop
// aggregation; GEMMs consume fp32 agg buffers) — halves the L2-bound gather
// traffic that dominates the aggregate kernels. Accumulation stays fp32.
// GEMMs: cp.async double-buffered k-chunk pipeline. Relu in agg64 epilogue.
// ---------------------------------------------------------------------------

#define N_NODES 100000
#define N_EDGES 1600000
#define SCAN_BS 1024
#define SCAN_NB ((N_NODES + SCAN_BS - 1) / SCAN_BS)

__device__ __align__(16) __half g_h[N_NODES * 64];   // fp16 messages
__device__ __align__(16) float  g_aggA[N_NODES * 64];
__device__ __align__(16) float  g_aggB[N_NODES * 64];
__device__ float  g_dinv[N_NODES];
__device__ int    g_cnt[N_NODES];
__device__ int    g_rowptr[N_NODES + 1];
__device__ int    g_cursor[N_NODES];
__device__ int    g_bsum[SCAN_NB];
__device__ __align__(8) float2 g_epack[N_EDGES];  // CSR: {src bits, coef}
__device__ int    g_is64;

#define FMA2(d, a, b) \
    asm("fma.rn.f32x2 %0, %1, %2, %0;" : "+l"(d) : "l"(a), "l"(b))
#define PACKXX(d, x) \
    asm("mov.b64 %0, {%1, %1};" : "=l"(d) : "f"(x))
#define UNPACK2(lo, hi, v) \
    asm("mov.b64 {%0, %1}, %2;" : "=f"(lo), "=f"(hi) : "l"(v))
#define CP_ASYNC16(dst, src) \
    asm volatile("cp.async.ca.shared.global [%0], [%1], 16;" \
                 :: "r"(dst), "l"(src) : "memory")
#define CP_COMMIT() asm volatile("cp.async.commit_group;" ::: "memory")
#define CP_WAIT(nn) asm volatile("cp.async.wait_group %0;" :: "n"(nn) : "memory")

// ---------------------------------------------------------------------------
// Prep (byte-identical to champion)
// ---------------------------------------------------------------------------
__global__ void detect_zero_kernel(const int* __restrict__ w, int n) {
    int i = blockIdx.x * blockDim.x + threadIdx.x;
    if (i < n) g_cnt[i] = 0;
    if (blockIdx.x == 0) {
        __shared__ int nonzero;
        if (threadIdx.x == 0) nonzero = 0;
        __syncthreads();
        if (w[2 * threadIdx.x + 1] != 0) atomicOr(&nonzero, 1);
        __syncthreads();
        if (threadIdx.x == 0) g_is64 = (nonzero == 0) ? 1 : 0;
    }
}

__global__ void hist_kernel(const void* __restrict__ ei, int ne) {
    int e = blockIdx.x * blockDim.x + threadIdx.x;
    if (e >= ne) return;
    int d;
    if (g_is64) {
        d = (int)((const long long*)ei)[ne + e];
    } else {
        d = ((const int*)ei)[ne + e];
    }
    atomicAdd(&g_cnt[d], 1);
}

__global__ void scan1_kernel(int n) {
    __shared__ int sm[SCAN_BS];
    int t = threadIdx.x;
    int i = blockIdx.x * SCAN_BS + t;
    int v = (i < n) ? g_cnt[i] : 0;
    sm[t] = v;
    __syncthreads();
    for (int off = 1; off < SCAN_BS; off <<= 1) {
        int u = (t >= off) ? sm[t - off] : 0;
        __syncthreads();
        sm[t] += u;
        __syncthreads();
    }
    if (i < n) {
        g_rowptr[i] = sm[t] - v;
        g_dinv[i]   = rsqrtf((float)v + 1.0f);
    }
    if (t == SCAN_BS - 1) g_bsum[blockIdx.x] = sm[t];
}

__global__ void scan3_kernel(int n, int ne) {
    __shared__ int s_pref;
    const int t = threadIdx.x;
    const int b = (blockIdx.x * 256) / SCAN_BS;
    if (t < 32) {
        int v = 0;
        for (int j = t; j < b; j += 32) v += g_bsum[j];
#pragma unroll
        for (int o = 16; o; o >>= 1) v += __shfl_down_sync(0xffffffffu, v, o);
        if (t == 0) s_pref = v;
    }
    __syncthreads();
    int i = blockIdx.x * 256 + t;
    if (i < n) {
        int r = g_rowptr[i] + s_pref;
        g_rowptr[i] = r;
        g_cursor[i] = r;
    }
    if (i == 0) g_rowptr[n] = ne;
}

__global__ void place_kernel(const void* __restrict__ ei, int ne) {
    int e = blockIdx.x * blockDim.x + threadIdx.x;
    if (e >= ne) return;
    int s, d;
    if (g_is64) {
        const long long* p = (const long long*)ei;
        s = (int)p[e];
        d = (int)p[ne + e];
    } else {
        const int* p = (const int*)ei;
        s = p[e];
        d = p[ne + e];
    }
    int pos = atomicAdd(&g_cursor[d], 1);
    g_epack[pos] = make_float2(__int_as_float(s), g_dinv[s] * g_dinv[d]);
}

// ---------------------------------------------------------------------------
// Pipelined register-blocked GEMM, DOUT=64, 128 threads; fp16 output.
// ---------------------------------------------------------------------------
template <int DIN>
__global__ void __launch_bounds__(128) gemm64p_kernel(const float* __restrict__ in,
                                                      const float* __restrict__ W,
                                                      __half* __restrict__ h_out,
                                                      int n)
{
    constexpr int DOUT = 64;
    constexpr int TILE_R = 128;
    constexpr int KC = 32;
    constexpr int XS = KC + 4;
    constexpr int NCH = DIN / KC;
    constexpr int CHUNK_V4 = TILE_R * KC / 4;

    extern __shared__ float sm[];
    float* sW = sm;
    float* sX = sm + DIN * DOUT;

    const int tid  = threadIdx.x;
    const int row0 = blockIdx.x * TILE_R;
    const unsigned int sx_base = (unsigned int)__cvta_generic_to_shared(sX);

    const float4* Wv  = (const float4*)W;
    float4*       sWv = (float4*)sW;
    for (int i = tid; i < DIN * DOUT / 4; i += 128) sWv[i] = Wv[i];

    auto stage = [&](int ck, int buf) {
#pragma unroll
        for (int i = tid; i < CHUNK_V4; i += 128) {
            int r = i >> 3;
            int q = i & 7;
            int gr = row0 + r;
            if (gr < n) {
                unsigned int dst = sx_base +
                    (unsigned int)((buf * TILE_R * XS + r * XS + q * 4) * 4);
                const float* src = &in[gr * DIN + ck * KC + q * 4];
                CP_ASYNC16(dst, src);
            }
        }
        CP_COMMIT();
    };

    stage(0, 0);

    const int cg = tid & 7;
    const int tr = tid >> 3;

    unsigned long long acc[8][4];
#pragma unroll
    for (int j = 0; j < 8; j++)
#pragma unroll
        for (int p = 0; p < 4; p++) acc[j][p] = 0ULL;

    const ulonglong2* wv = (const ulonglong2*)sW;

    for (int ck = 0; ck < NCH; ck++) {
        if (ck + 1 < NCH) {
            stage(ck + 1, (ck + 1) & 1);
            CP_WAIT(1);
        } else {
            CP_WAIT(0);
        }
        __syncthreads();

        const float* xbase = sX + (ck & 1) * TILE_R * XS + tr * XS;
#pragma unroll
        for (int k = 0; k < KC; k++) {
            ulonglong2 wA = wv[(ck * KC + k) * (DOUT / 4) + cg];
            ulonglong2 wB = wv[(ck * KC + k) * (DOUT / 4) + 8 + cg];
#pragma unroll
            for (int j = 0; j < 8; j++) {
                float xv = xbase[j * 16 * XS + k];
                unsigned long long xx;
                PACKXX(xx, xv);
                FMA2(acc[j][0], xx, wA.x);
                FMA2(acc[j][1], xx, wA.y);
                FMA2(acc[j][2], xx, wB.x);
                FMA2(acc[j][3], xx, wB.y);
            }
        }
        __syncthreads();
    }

    uint2* hp = (uint2*)h_out;            // 4 halves per uint2; 16 per row
#pragma unroll
    for (int j = 0; j < 8; j++) {
        int r = row0 + tr + 16 * j;
        if (r < n) {
            float a0, a1, b0, b1;
            UNPACK2(a0, a1, acc[j][0]);
            UNPACK2(b0, b1, acc[j][1]);
            __half2 ha = __floats2half2_rn(a0, a1);
            __half2 hb = __floats2half2_rn(b0, b1);
            uint2 pk;
            pk.x = *(unsigned int*)&ha;
            pk.y = *(unsigned int*)&hb;
            hp[r * 16 + cg] = pk;
            UNPACK2(a0, a1, acc[j][2]);
            UNPACK2(b0, b1, acc[j][3]);
            ha = __floats2half2_rn(a0, a1);
            hb = __floats2half2_rn(b0, b1);
            pk.x = *(unsigned int*)&ha;
            pk.y = *(unsigned int*)&hb;
            hp[r * 16 + 8 + cg] = pk;
        }
    }
}

// ---------------------------------------------------------------------------
// GEMM for DOUT=40 (layer 3), fp16 output — smem-walk version.
// ---------------------------------------------------------------------------
template <int DIN, int DOUT, int CGROUPS, int TILE_R>
__global__ void gemm_kernel(const float* __restrict__ in,
                            const float* __restrict__ W,
                            __half* __restrict__ h_out,
                            int n)
{
    constexpr int CP = DOUT / CGROUPS;
    constexpr int XS = DIN + 1;
    extern __shared__ float sm[];
    float* sW = sm;
    float* sX = sm + DIN * DOUT;

    const int tid  = threadIdx.x;
    const int nthr = blockDim.x;
    const int row0 = blockIdx.x * TILE_R;

    for (int i = tid; i < DIN * DOUT; i += nthr) sW[i] = W[i];
    for (int i = tid; i < TILE_R * DIN; i += nthr) {
        int r = i / DIN;
        int k = i - r * DIN;
        int gr = row0 + r;
        float v = 0.0f;
        if (gr < n) v = in[gr * DIN + k];
        sX[r * XS + k] = v;
    }
    __syncthreads();

    const int rl = tid / CGROUPS;
    const int cg = tid - rl * CGROUPS;
    const int c0 = cg * CP;

    float acc[CP];
#pragma unroll
    for (int j = 0; j < CP; j++) acc[j] = 0.0f;

    const float* xrow = &sX[rl * XS];
#pragma unroll 4
    for (int k = 0; k < DIN; k++) {
        float xv = xrow[k];
        const float4* wrow = reinterpret_cast<const float4*>(&sW[k * DOUT + c0]);
#pragma unroll
        for (int j4 = 0; j4 < CP / 4; j4++) {
            float4 w = wrow[j4];
            acc[j4 * 4 + 0] = fmaf(xv, w.x, acc[j4 * 4 + 0]);
            acc[j4 * 4 + 1] = fmaf(xv, w.y, acc[j4 * 4 + 1]);
            acc[j4 * 4 + 2] = fmaf(xv, w.z, acc[j4 * 4 + 2]);
            acc[j4 * 4 + 3] = fmaf(xv, w.w, acc[j4 * 4 + 3]);
        }
    }

    const int r = row0 + rl;
    if (r < n) {
#pragma unroll
        for (int j2 = 0; j2 < CP / 2; j2++) {
            __half2 hv = __floats2half2_rn(acc[j2 * 2], acc[j2 * 2 + 1]);
            *(__half2*)&h_out[r * DOUT + c0 + j2 * 2] = hv;
        }
    }
}

// ---------------------------------------------------------------------------
// Aggregation DOUT=64: warp per node, 2 edges/iter (half-warps), fp16 gather
// (uint2 = 4 halves per lane), fp32 accumulate, +relu epilogue.
// ---------------------------------------------------------------------------
__global__ void aggregate64_kernel(const __half* __restrict__ h,
                                   const float* __restrict__ bias,
                                   float* __restrict__ out,
                                   int n)
{
    int w = (blockIdx.x * blockDim.x + threadIdx.x) >> 5;
    if (w >= n) return;
    int lane = threadIdx.x & 31;
    int half_ = lane >> 4;
    int sub  = lane & 15;

    int c0 = g_rowptr[w];
    int c1 = g_rowptr[w + 1];

    const uint2* hp = (const uint2*)h;    // 16 uint2 (64 halves) per row
    float4 acc = make_float4(0.f, 0.f, 0.f, 0.f);

#pragma unroll 2
    for (int i = c0; i < c1; i += 2) {
        int e = i + half_;
        if (e < c1) {
            float2 pk = g_epack[e];
            int   s = __float_as_int(pk.x);
            float c = pk.y;
            uint2 v = hp[s * 16 + sub];
            float2 f01 = __half22float2(*(__half2*)&v.x);
            float2 f23 = __half22float2(*(__half2*)&v.y);
            acc.x = fmaf(f01.x, c, acc.x);
            acc.y = fmaf(f01.y, c, acc.y);
            acc.z = fmaf(f23.x, c, acc.z);
            acc.w = fmaf(f23.y, c, acc.w);
        }
    }
    acc.x += __shfl_xor_sync(0xffffffffu, acc.x, 16);
    acc.y += __shfl_xor_sync(0xffffffffu, acc.y, 16);
    acc.z += __shfl_xor_sync(0xffffffffu, acc.z, 16);
    acc.w += __shfl_xor_sync(0xffffffffu, acc.w, 16);

    float di  = g_dinv[w];
    float di2 = di * di;
    uint2 hv = hp[w * 16 + sub];
    float2 s01 = __half22float2(*(__half2*)&hv.x);
    float2 s23 = __half22float2(*(__half2*)&hv.y);
    float4 bv = ((const float4*)bias)[sub];
    float4 r;
    r.x = fmaxf(fmaf(s01.x, di2, acc.x) + bv.x, 0.f);
    r.y = fmaxf(fmaf(s01.y, di2, acc.y) + bv.y, 0.f);
    r.z = fmaxf(fmaf(s23.x, di2, acc.z) + bv.z, 0.f);
    r.w = fmaxf(fmaf(s23.y, di2, acc.w) + bv.w, 0.f);
    if (half_ == 0) ((float4*)out)[w * 16 + sub] = r;
}

// ---------------------------------------------------------------------------
// Aggregation DOUT=40: warp per node; scalar fp16 loads (measured-best shape).
// Final output — NO relu.
// ---------------------------------------------------------------------------
__global__ void aggregate40_kernel(const __half* __restrict__ h,
                                   const float* __restrict__ bias,
                                   float* __restrict__ out,
                                   int n)
{
    int w = (blockIdx.x * blockDim.x + threadIdx.x) >> 5;
    if (w >= n) return;
    int lane = threadIdx.x & 31;

    int c0 = g_rowptr[w];
    int c1 = g_rowptr[w + 1];
    bool hi = (lane < 8);

    float a0 = 0.0f, a1 = 0.0f;
    for (int i = c0; i < c1; i++) {
        float2 pk = g_epack[i];
        int   s = __float_as_int(pk.x);
        float c = pk.y;
        const __half* hr = &h[s * 40];
        a0 = fmaf(__half2float(hr[lane]), c, a0);
        if (hi) a1 = fmaf(__half2float(hr[32 + lane]), c, a1);
    }

    float di  = g_dinv[w];
    float di2 = di * di;
    const __half* hs = &h[w * 40];
    out[w * 40 + lane] = fmaf(__half2float(hs[lane]), di2, a0) + bias[lane];
    if (hi)
        out[w * 40 + 32 + lane] =
            fmaf(__half2float(hs[32 + lane]), di2, a1) + bias[32 + lane];
}

// ---------------------------------------------------------------------------
// Launch (single stream; gemm1 at launch slot 4 for ncu visibility)
// ---------------------------------------------------------------------------
extern "C" void kernel_launch(void* const* d_in, const int* in_sizes, int n_in,
                              void* d_out, int out_size)
{
    const float* x  = (const float*)d_in[0];
    const void*  ei = d_in[1];
    const float* W1 = (const float*)d_in[2];
    const float* b1 = (const float*)d_in[3];
    const float* W2 = (const float*)d_in[4];
    const float* b2 = (const float*)d_in[5];
    const float* W3 = (const float*)d_in[6];
    const float* b3 = (const float*)d_in[7];
    float* out = (float*)d_out;

    const int N = in_sizes[0] / 128;   // 100000
    const int E = in_sizes[1] / 2;     // 1600000

    __half* h;
    float *aggA, *aggB;
    cudaGetSymbolAddress((void**)&h,    g_h);
    cudaGetSymbolAddress((void**)&aggA, g_aggA);
    cudaGetSymbolAddress((void**)&aggB, g_aggB);

    constexpr int TRB = 128;
    const int g2_grid  = (N + TRB - 1) / TRB;
    const int agg_grid = (N * 32 + 255) / 256;
    const int smem1 = (128 * 64 + 2 * TRB * 36) * (int)sizeof(float);  // 68KB
    const int smem2 = (64 * 64 + 2 * TRB * 36) * (int)sizeof(float);   // 52KB
    cudaFuncSetAttribute(gemm64p_kernel<128>,
                         cudaFuncAttributeMaxDynamicSharedMemorySize, smem1);
    cudaFuncSetAttribute(gemm64p_kernel<64>,
                         cudaFuncAttributeMaxDynamicSharedMemorySize, smem2);

    // --- prep (launches 1-3) ---
    detect_zero_kernel<<<(N + 255) / 256, 256>>>((const int*)ei, N);
    hist_kernel<<<(E + 255) / 256, 256>>>(ei, E);
    const int nb = (N + SCAN_BS - 1) / SCAN_BS;
    scan1_kernel<<<nb, SCAN_BS>>>(N);

    // --- launch 4: GEMM1 (independent of CSR prep; ncu captures slot 4) ---
    gemm64p_kernel<128><<<g2_grid, 128, smem1>>>(x, W1, h, N);

    // --- prep tail (launches 5-6) ---
    scan3_kernel<<<(N + 255) / 256, 256>>>(N, E);
    place_kernel<<<(E + 255) / 256, 256>>>(ei, E);

    // --- layer 1 aggregation (writes relu'd aggA) ---
    aggregate64_kernel<<<agg_grid, 256>>>(h, b1, aggA, N);

    // --- layer 2: 64 -> 64 ---
    gemm64p_kernel<64><<<g2_grid, 128, smem2>>>(aggA, W2, h, N);
    aggregate64_kernel<<<agg_grid, 256>>>(h, b2, aggB, N);

    // --- layer 3: 64 -> 40 (aggB already relu'd) ---
    constexpr int TR3 = 64;
    const int g3_grid = (N + TR3 - 1) / TR3;
    const int smem3 = (64 * 40 + TR3 * (64 + 1)) * (int)sizeof(float);
    gemm_kernel<64, 40, 5, TR3><<<g3_grid, TR3 * 5, smem3>>>(aggB, W3, h, N);
    aggregate40_kernel<<<agg_grid, 256>>>(h, b3, out, N);
}